// round 1
// baseline (speedup 1.0000x reference)
#include <cuda_runtime.h>
#include <cuda_bf16.h>
#include <math.h>

// Problem constants
#define B_   2
#define S_   2048
#define E_   2048
#define H_   16
#define KVH_ 4
#define D_   128
#define M_   (B_ * S_)        // 4096 rows
#define KVN_ (2 * KVH_ * D_)  // 1024

// ---------------- scratch (device globals; no allocs allowed) ----------------
__device__ float g_qproj[(size_t)M_ * E_];    // [B*S, H*D]  (=[B,S,H,D])
__device__ float g_kvproj[(size_t)M_ * KVN_]; // [B*S, 2*KVH*D]
__device__ float g_attno[(size_t)M_ * E_];    // [B*S, H*D]

// ======================= SGEMM: C = A @ W^T (+bias) ==========================
// A: [M,K] row-major, W: [N,K] row-major, C: [M,N]. M,N mult of 128, K mult of 16.
__global__ void __launch_bounds__(256) sgemm_nt(const float* __restrict__ A,
                                                const float* __restrict__ W,
                                                const float* __restrict__ bias,
                                                float* __restrict__ C,
                                                int M, int N, int K) {
    __shared__ float As[16][128];
    __shared__ float Bs[16][128];
    const int tid = threadIdx.x;
    const int tx = tid & 15;   // n sub-tile
    const int ty = tid >> 4;   // m sub-tile
    const int m0 = blockIdx.y * 128;
    const int n0 = blockIdx.x * 128;
    const int lr = tid >> 2;          // 0..63
    const int lc = (tid & 3) << 2;    // 0,4,8,12

    float acc[8][8];
#pragma unroll
    for (int i = 0; i < 8; i++)
#pragma unroll
        for (int j = 0; j < 8; j++) acc[i][j] = 0.f;

    for (int k0 = 0; k0 < K; k0 += 16) {
#pragma unroll
        for (int r = 0; r < 2; r++) {
            int row = lr + 64 * r;
            float4 av = *(const float4*)&A[(size_t)(m0 + row) * K + k0 + lc];
            As[lc + 0][row] = av.x; As[lc + 1][row] = av.y;
            As[lc + 2][row] = av.z; As[lc + 3][row] = av.w;
            float4 bv = *(const float4*)&W[(size_t)(n0 + row) * K + k0 + lc];
            Bs[lc + 0][row] = bv.x; Bs[lc + 1][row] = bv.y;
            Bs[lc + 2][row] = bv.z; Bs[lc + 3][row] = bv.w;
        }
        __syncthreads();
#pragma unroll
        for (int kk = 0; kk < 16; kk++) {
            float a[8], b[8];
            float4 t;
            t = *(float4*)&As[kk][ty * 8];     a[0]=t.x; a[1]=t.y; a[2]=t.z; a[3]=t.w;
            t = *(float4*)&As[kk][ty * 8 + 4]; a[4]=t.x; a[5]=t.y; a[6]=t.z; a[7]=t.w;
            t = *(float4*)&Bs[kk][tx * 8];     b[0]=t.x; b[1]=t.y; b[2]=t.z; b[3]=t.w;
            t = *(float4*)&Bs[kk][tx * 8 + 4]; b[4]=t.x; b[5]=t.y; b[6]=t.z; b[7]=t.w;
#pragma unroll
            for (int i = 0; i < 8; i++)
#pragma unroll
                for (int j = 0; j < 8; j++) acc[i][j] += a[i] * b[j];
        }
        __syncthreads();
    }
#pragma unroll
    for (int i = 0; i < 8; i++) {
        int m = m0 + ty * 8 + i;
#pragma unroll
        for (int j = 0; j < 8; j += 4) {
            int n = n0 + tx * 8 + j;
            float4 v;
            float b0 = bias ? bias[n + 0] : 0.f;
            float b1 = bias ? bias[n + 1] : 0.f;
            float b2 = bias ? bias[n + 2] : 0.f;
            float b3 = bias ? bias[n + 3] : 0.f;
            v.x = acc[i][j + 0] + b0;
            v.y = acc[i][j + 1] + b1;
            v.z = acc[i][j + 2] + b2;
            v.w = acc[i][j + 3] + b3;
            *(float4*)&C[(size_t)m * N + n] = v;
        }
    }
}

// ================================ RoPE (in place) ============================
// t: [M_, rowStride]; head h occupies cols h*128..h*128+127. s = m % S_.
__global__ void rope_kernel(float* __restrict__ t, int nHeads, int rowStride) {
    int idx = blockIdx.x * blockDim.x + threadIdx.x;
    int total = M_ * nHeads * 64;
    if (idx >= total) return;
    int i = idx & 63;
    int h = (idx >> 6) % nHeads;
    int m = idx / (64 * nHeads);
    int s = m & (S_ - 1);
    float inv = powf(10000.0f, -(float)i * (1.0f / 64.0f));
    float fr = (float)s * inv;
    float sn, cs;
    sincosf(fr, &sn, &cs);
    float* p = t + (size_t)m * rowStride + h * 128 + i;
    float v1 = p[0], v2 = p[64];
    p[0]  = v1 * cs - v2 * sn;
    p[64] = v2 * cs + v1 * sn;
}

// ============================ Flash attention ================================
// 256 threads = 8 warps; each warp owns 4 q rows; BK=64 K/V tile.
// Q: [B*S, H*D] (RoPE'd), KV: [B*S, 2*KVH*D] (K RoPE'd), O: [B*S, H*D].
#define BKf 64
#define KT_STRIDE 65
// smem floats: q 32*128, Kt 128*65, Vs 64*128, p 8*4*64
#define FLASH_SMEM_FLOATS (32 * 128 + 128 * KT_STRIDE + 64 * 128 + 8 * 4 * 64)

extern __shared__ float fsm[];
__global__ void __launch_bounds__(256) flash_kernel(const float* __restrict__ Q,
                                                    const float* __restrict__ KV,
                                                    float* __restrict__ O) {
    float* q_s = fsm;                        // [32][128]
    float* Kt  = q_s + 32 * 128;             // [128][65] transposed K
    float* Vs  = Kt + 128 * KT_STRIDE;       // [64][128]
    float* p_s = Vs + 64 * 128;              // [8*4][64]

    const int tid = threadIdx.x;
    const int warp = tid >> 5, lane = tid & 31;
    const int bh = blockIdx.y;               // 0..31
    const int b = bh >> 4, h = bh & 15;
    const int kvh = h >> 2;
    const int q0 = blockIdx.x * 32;
    const float scale = 0.08838834764831845f;  // 1/sqrt(128)

    // load 32 q rows
    for (int i = tid; i < 32 * (D_ / 4); i += 256) {
        int r = i >> 5;              // row 0..31
        int c = (i & 31) << 2;       // col 0..124
        *(float4*)&q_s[r * D_ + c] =
            *(const float4*)&Q[(size_t)(b * S_ + q0 + r) * E_ + h * 128 + c];
    }

    float m_r[4], l_r[4], o_acc[4][4];
#pragma unroll
    for (int r = 0; r < 4; r++) {
        m_r[r] = -1e30f; l_r[r] = 0.f;
#pragma unroll
        for (int i = 0; i < 4; i++) o_acc[r][i] = 0.f;
    }

    const float* Kbase = KV + (size_t)b * S_ * KVN_ + kvh * 128;
    const float* Vbase = KV + (size_t)b * S_ * KVN_ + KVH_ * 128 + kvh * 128;

    for (int kt = 0; kt < S_; kt += BKf) {
        __syncthreads();
        // load K (transposed) + V tiles: 64 rows x 128
#pragma unroll
        for (int it = 0; it < 8; it++) {
            int li = tid + it * 256;     // 0..2047
            int j = li >> 5;             // k row 0..63
            int d = (li & 31) << 2;
            float4 k4 = *(const float4*)&Kbase[(size_t)(kt + j) * KVN_ + d];
            Kt[(d + 0) * KT_STRIDE + j] = k4.x;
            Kt[(d + 1) * KT_STRIDE + j] = k4.y;
            Kt[(d + 2) * KT_STRIDE + j] = k4.z;
            Kt[(d + 3) * KT_STRIDE + j] = k4.w;
            float4 v4 = *(const float4*)&Vbase[(size_t)(kt + j) * KVN_ + d];
            *(float4*)&Vs[j * D_ + d] = v4;
        }
        __syncthreads();

        // phase 1: scores for columns (lane, lane+32) x 4 rows
        float s[4][2];
#pragma unroll
        for (int r = 0; r < 4; r++) { s[r][0] = 0.f; s[r][1] = 0.f; }
#pragma unroll
        for (int d4 = 0; d4 < D_; d4 += 4) {
            float k0[4], k1[4];
#pragma unroll
            for (int i = 0; i < 4; i++) {
                k0[i] = Kt[(d4 + i) * KT_STRIDE + lane];
                k1[i] = Kt[(d4 + i) * KT_STRIDE + lane + 32];
            }
#pragma unroll
            for (int r = 0; r < 4; r++) {
                float4 qv = *(float4*)&q_s[(warp * 4 + r) * D_ + d4];
                s[r][0] += qv.x * k0[0] + qv.y * k0[1] + qv.z * k0[2] + qv.w * k0[3];
                s[r][1] += qv.x * k1[0] + qv.y * k1[1] + qv.z * k1[2] + qv.w * k1[3];
            }
        }
        // online softmax per row
#pragma unroll
        for (int r = 0; r < 4; r++) {
            float s0 = s[r][0] * scale, s1 = s[r][1] * scale;
            float mx = fmaxf(s0, s1);
#pragma unroll
            for (int off = 16; off; off >>= 1)
                mx = fmaxf(mx, __shfl_xor_sync(0xffffffffu, mx, off));
            float mnew = fmaxf(m_r[r], mx);
            float p0 = expf(s0 - mnew), p1 = expf(s1 - mnew);
            float corr = expf(m_r[r] - mnew);
            float ps = p0 + p1;
#pragma unroll
            for (int off = 16; off; off >>= 1)
                ps += __shfl_xor_sync(0xffffffffu, ps, off);
            l_r[r] = l_r[r] * corr + ps;
            m_r[r] = mnew;
#pragma unroll
            for (int i = 0; i < 4; i++) o_acc[r][i] *= corr;
            p_s[(warp * 4 + r) * 64 + lane] = p0;
            p_s[(warp * 4 + r) * 64 + lane + 32] = p1;
        }
        __syncwarp();
        // phase 2: O += P @ V  (lane owns d = lane*4..lane*4+3)
#pragma unroll 4
        for (int j = 0; j < BKf; j++) {
            float4 vv = *(float4*)&Vs[j * D_ + lane * 4];
#pragma unroll
            for (int r = 0; r < 4; r++) {
                float pj = p_s[(warp * 4 + r) * 64 + j];
                o_acc[r][0] += pj * vv.x;
                o_acc[r][1] += pj * vv.y;
                o_acc[r][2] += pj * vv.z;
                o_acc[r][3] += pj * vv.w;
            }
        }
    }
    // epilogue
#pragma unroll
    for (int r = 0; r < 4; r++) {
        float inv = 1.f / l_r[r];
        float4 ov;
        ov.x = o_acc[r][0] * inv; ov.y = o_acc[r][1] * inv;
        ov.z = o_acc[r][2] * inv; ov.w = o_acc[r][3] * inv;
        int srow = q0 + warp * 4 + r;
        *(float4*)&O[(size_t)(b * S_ + srow) * E_ + h * 128 + lane * 4] = ov;
    }
}

// ================================ launch =====================================
extern "C" void kernel_launch(void* const* d_in, const int* in_sizes, int n_in,
                              void* d_out, int out_size) {
    const float* x   = (const float*)d_in[0];
    const float* Wq  = (const float*)d_in[1];
    const float* bq  = (const float*)d_in[2];
    const float* Wkv = (const float*)d_in[3];
    const float* bkv = (const float*)d_in[4];
    const float* Wo  = (const float*)d_in[5];
    float* out = (float*)d_out;

    float *qb, *kvb, *ob;
    cudaGetSymbolAddress((void**)&qb,  g_qproj);
    cudaGetSymbolAddress((void**)&kvb, g_kvproj);
    cudaGetSymbolAddress((void**)&ob,  g_attno);

    // Q projection: [4096,2048] = x @ Wq^T + bq
    sgemm_nt<<<dim3(E_ / 128, M_ / 128), 256>>>(x, Wq, bq, qb, M_, E_, E_);
    // KV projection: [4096,1024]
    sgemm_nt<<<dim3(KVN_ / 128, M_ / 128), 256>>>(x, Wkv, bkv, kvb, M_, KVN_, E_);

    // RoPE on Q and K
    {
        int totq = M_ * H_ * 64;
        rope_kernel<<<(totq + 255) / 256, 256>>>(qb, H_, E_);
        int totk = M_ * KVH_ * 64;
        rope_kernel<<<(totk + 255) / 256, 256>>>(kvb, KVH_, KVN_);
    }

    // Flash attention
    {
        size_t smem = FLASH_SMEM_FLOATS * sizeof(float);
        static bool attr_set = false;
        cudaFuncSetAttribute(flash_kernel,
                             cudaFuncAttributeMaxDynamicSharedMemorySize,
                             (int)smem);
        (void)attr_set;
        flash_kernel<<<dim3(S_ / 32, B_ * H_), 256, smem>>>(qb, kvb, ob);
    }

    // Output projection: out = attno @ Wo^T
    sgemm_nt<<<dim3(E_ / 128, M_ / 128), 256>>>(ob, Wo, nullptr, out, M_, E_, E_);
}